// round 1
// baseline (speedup 1.0000x reference)
#include <cuda_runtime.h>
#include <math.h>

// Problem constants (fixed by the dataset)
#define TT 1600
#define NN 32
#define CC 512
#define SS 200
#define LL (2 * SS + 1)   // 401
#define NEGV (-1e30f)

// Scratch: per-example normalized loss (device global -> no allocation)
__device__ float g_per_ex[NN];

__global__ void __launch_bounds__(512, 1)
ctc_forward_kernel(const float* __restrict__ lp,      // (T, N, C)
                   const int*   __restrict__ targets, // (N, S)
                   const int*   __restrict__ input_lens,  // (N)
                   const int*   __restrict__ target_lens) // (N)
{
    __shared__ float sh_row[2][CC];        // emit rows, double buffered
    __shared__ float sh_alpha[2][LL + 2];  // alpha with 2-pad at front
    __shared__ int   sh_ext[LL];
    __shared__ unsigned char sh_allow[LL];

    const int n   = blockIdx.x;
    const int tid = threadIdx.x;
    const float* base = lp + (size_t)n * CC;  // row for (t, n) at base + t*N*C

    // ---- build extended label sequence ----
    for (int s = tid; s < LL; s += 512) {
        sh_ext[s] = (s & 1) ? targets[n * SS + (s >> 1)] : 0;
    }
    // row t = 0
    sh_row[0][tid] = base[tid];
    const int tl = target_lens[n];
    const int il = input_lens[n];
    __syncthreads();

    // ---- allow-skip mask, alpha0, pads ----
    for (int s = tid; s < LL; s += 512) {
        sh_allow[s] = (s >= 2) && (sh_ext[s] != 0) && (sh_ext[s] != sh_ext[s - 2]);
    }
    if (tid < 2) { sh_alpha[0][tid] = NEGV; sh_alpha[1][tid] = NEGV; }
    for (int s = tid; s < LL; s += 512) {
        float v = NEGV;
        if (s == 0) v = sh_row[0][0];
        else if (s == 1 && tl >= 1) v = sh_row[0][sh_ext[1]];
        sh_alpha[0][s + 2] = v;
    }

    // ---- prefetch pipeline: rows 1..3 ----
    const size_t NC = (size_t)NN * CC;
    float r1 = base[1 * NC + tid];
    float regA = base[(size_t)min(2, TT - 1) * NC + tid];
    float regB = base[(size_t)min(3, TT - 1) * NC + tid];
    sh_row[1][tid] = r1;
    __syncthreads();

    // ---- main trellis loop ----
    // invariant at top of iter t: sh_row[t&1] holds row t,
    // regA holds row t+1, regB holds row t+2 (in flight / arrived)
    for (int t = 1; t < TT; ++t) {
        const int buf = t & 1;
        const float* __restrict__ row = sh_row[buf];
        const float* __restrict__ ap  = sh_alpha[buf ^ 1];
        float* __restrict__ an        = sh_alpha[buf];

        if (tid < LL) {
            const int s = tid;
            const float a0 = ap[s + 2];
            const float a1 = ap[s + 1];
            const float a2 = sh_allow[s] ? ap[s] : NEGV;
            const float emit = row[sh_ext[s]];
            const float m = fmaxf(a0, fmaxf(a1, a2));
            const float sum = __expf(a0 - m) + __expf(a1 - m) + __expf(a2 - m);
            const float nv = m + __logf(sum) + emit;
            an[s + 2] = (t < il) ? nv : a0;
        }

        // rotate prefetch: store row t+1, load row t+3
        sh_row[buf ^ 1][tid] = regA;
        regA = regB;
        const int tn = min(t + 3, TT - 1);
        regB = base[(size_t)tn * NC + tid];
        __syncthreads();
    }

    // ---- readout ----
    if (tid == 0) {
        const float* a = sh_alpha[(TT - 1) & 1];
        const int i_last = 2 * tl;
        const float al  = a[i_last + 2];
        const float apv = (tl > 0) ? a[max(i_last - 1, 0) + 2] : NEGV;
        const float m = fmaxf(al, apv);
        float loss = -(m + __logf(__expf(al - m) + __expf(apv - m)));
        if (!(loss < 1e29f)) loss = 0.0f;   // zero_infinity (also kills NaN)
        const float norm = sqrtf(fmaxf((float)tl, 1.0f));  // ALPHA = 0.5
        g_per_ex[n] = loss / norm;
    }
}

__global__ void reduce_mean_kernel(float* __restrict__ out)
{
    const int tid = threadIdx.x;
    float v = g_per_ex[tid];
#pragma unroll
    for (int o = 16; o; o >>= 1) v += __shfl_down_sync(0xffffffffu, v, o);
    if (tid == 0) out[0] = v / (float)NN;
}

extern "C" void kernel_launch(void* const* d_in, const int* in_sizes, int n_in,
                              void* d_out, int out_size)
{
    const float* log_probs   = (const float*)d_in[0];
    const int*   targets     = (const int*)d_in[1];
    const int*   input_lens  = (const int*)d_in[2];
    const int*   target_lens = (const int*)d_in[3];
    float* out = (float*)d_out;

    ctc_forward_kernel<<<NN, 512>>>(log_probs, targets, input_lens, target_lens);
    reduce_mean_kernel<<<1, 32>>>(out);
}

// round 2
// speedup vs baseline: 1.5244x; 1.5244x over previous
#include <cuda_runtime.h>
#include <math.h>

// Problem constants (fixed by dataset)
#define TT 1600
#define NN 32
#define CC 512
#define SS 200
#define LL (2 * SS + 1)   // 401
#define LOG2E 1.4426950408889634f
#define LN2   0.6931471805599453f
#define NEG2  (-1.0e30f * 1.4426950408889634f)  // NEG in log2 domain (finite)

__device__ float g_per_ex[NN];

__device__ __forceinline__ float ex2f(float x) {
    float y; asm("ex2.approx.ftz.f32 %0, %1;" : "=f"(y) : "f"(x)); return y;
}
__device__ __forceinline__ float lg2f(float x) {
    float y; asm("lg2.approx.ftz.f32 %0, %1;" : "=f"(y) : "f"(x)); return y;
}
__device__ __forceinline__ void cp_async4(void* smem_dst, const void* gmem_src) {
    unsigned s = (unsigned)__cvta_generic_to_shared(smem_dst);
    asm volatile("cp.async.ca.shared.global [%0], [%1], 4;" :: "r"(s), "l"(gmem_src));
}
__device__ __forceinline__ void cp_commit() {
    asm volatile("cp.async.commit_group;");
}
template<int N>
__device__ __forceinline__ void cp_wait() {
    asm volatile("cp.async.wait_group %0;" :: "n"(N));
}

__global__ void __launch_bounds__(512, 1)
ctc_forward_kernel(const float* __restrict__ lp,       // (T, N, C)
                   const int*   __restrict__ targets,  // (N, S)
                   const int*   __restrict__ input_lens,
                   const int*   __restrict__ target_lens)
{
    __shared__ float rowbuf[4][CC];      // ring of emit rows (raw log-probs)
    __shared__ float ab[2][LL + 2];      // alpha ping-pong (log2 domain), 2-pad front

    const int n   = blockIdx.x;
    const int tid = threadIdx.x;
    const size_t NC = (size_t)NN * CC;
    const float* __restrict__ base = lp + (size_t)n * CC;   // + t*NC for row t

    const int tl = target_lens[n];
    const int il = input_lens[n];

    // ---- per-thread loop-invariant state (registers) ----
    const int  s      = tid;
    const bool active = (s < LL);
    int  myExt  = 0;
    bool allow  = false;
    if (active && (s & 1)) {
        myExt = targets[n * SS + (s >> 1)];
        if (s >= 3) allow = (myExt != targets[n * SS + (s >> 1) - 1]);
    }

    // alpha pads (never rewritten: loop writes go to index >= 2)
    if (tid < 2) { ab[0][tid] = NEG2; ab[1][tid] = NEG2; }

    // ---- alpha_0 in registers (log2 domain) ----
    float alphaReg = NEG2;
    if (s == 0) alphaReg = base[0] * LOG2E;                       // row0[blank]
    else if (s == 1 && tl >= 1) alphaReg = base[myExt] * LOG2E;   // row0[l1]

    // ---- cp.async prologue: rows 1..3 into ring slots 1..3 ----
#pragma unroll
    for (int r = 1; r <= 3; ++r) {
        cp_async4(&rowbuf[r & 3][tid], base + (size_t)r * NC + tid);
        cp_commit();
    }

    // ---- main trellis ----
    for (int t = 1; t < TT; ++t) {
        // publish a_{t-1}
        if (active) ab[(t - 1) & 1][s + 2] = alphaReg;
        cp_wait<2>();          // row t complete
        __syncthreads();       // alpha + row t visible to all

        const float* __restrict__ row = rowbuf[t & 3];
        const float* __restrict__ ap  = ab[(t - 1) & 1];

        float nv = alphaReg;
        if (active) {
            const float emit = row[myExt] * LOG2E;     // issue gather early
            const float a1   = ap[s + 1];
            const float a2   = allow ? ap[s] : NEG2;
            const float a0   = alphaReg;
            const float hi  = fmaxf(a0, a1);
            const float lo  = fminf(a0, a1);
            const float m   = fmaxf(hi, a2);
            const float mid = fminf(hi, a2);
            const float sum = 1.0f + ex2f(lo - m) + ex2f(mid - m);
            nv = m + lg2f(sum) + emit;
            alphaReg = (t < il) ? nv : a0;
        }

        // prefetch row t+3 into the slot just freed (row t-1's buffer)
        if (t + 3 < TT)
            cp_async4(&rowbuf[(t + 3) & 3][tid], base + (size_t)(t + 3) * NC + tid);
        cp_commit();           // keep group count aligned (empty groups OK)
    }

    // ---- readout: stash final alpha, thread 0 combines ----
    if (active) ab[1][s + 2] = alphaReg;
    __syncthreads();
    if (tid == 0) {
        const float* a = ab[1];
        const int i_last = 2 * tl;
        const float al  = a[i_last + 2];
        const float apv = (tl > 0) ? a[i_last + 1] : NEG2;   // index (i_last-1)+2
        const float m   = fmaxf(al, apv);
        const float lo  = fminf(al, apv);
        float loss = -LN2 * (m + lg2f(1.0f + ex2f(lo - m)));
        if (!(loss < 1e29f)) loss = 0.0f;                    // zero_infinity (+NaN kill)
        const float norm = sqrtf(fmaxf((float)tl, 1.0f));    // ALPHA = 0.5
        g_per_ex[n] = loss / norm;
    }
}

__global__ void reduce_mean_kernel(float* __restrict__ out)
{
    const int tid = threadIdx.x;
    float v = g_per_ex[tid];
#pragma unroll
    for (int o = 16; o; o >>= 1) v += __shfl_down_sync(0xffffffffu, v, o);
    if (tid == 0) out[0] = v / (float)NN;
}

extern "C" void kernel_launch(void* const* d_in, const int* in_sizes, int n_in,
                              void* d_out, int out_size)
{
    const float* log_probs   = (const float*)d_in[0];
    const int*   targets     = (const int*)d_in[1];
    const int*   input_lens  = (const int*)d_in[2];
    const int*   target_lens = (const int*)d_in[3];
    float* out = (float*)d_out;

    ctc_forward_kernel<<<NN, 512>>>(log_probs, targets, input_lens, target_lens);
    reduce_mean_kernel<<<1, 32>>>(out);
}